// round 1
// baseline (speedup 1.0000x reference)
#include <cuda_runtime.h>

#define S 8192
#define D 64
#define H 32        // b*n = 4*8
#define SCALE 0.125f // 64^-0.5
#define SCHUNK 512  // s elements per ctx block
#define TS 32       // s-tile inside ctx block

// Scratch (allocation-free rule: __device__ globals)
__device__ float g_C[H * D * D];  // per-head 64x64 context numerator
__device__ float g_Z[H * D];      // per-head row sums of exp(k)

// ---- packed f32x2 helpers ----
__device__ __forceinline__ unsigned long long pack2(float x, float y) {
    unsigned long long r;
    asm("mov.b64 %0, {%1, %2};" : "=l"(r) : "f"(x), "f"(y));
    return r;
}
__device__ __forceinline__ void unpack2(unsigned long long v, float &x, float &y) {
    asm("mov.b64 {%0, %1}, %2;" : "=f"(x), "=f"(y) : "l"(v));
}
__device__ __forceinline__ void fma2(unsigned long long &d, unsigned long long a,
                                     unsigned long long b) {
    asm("fma.rn.f32x2 %0, %1, %2, %0;" : "+l"(d) : "l"(a), "l"(b));
}
__device__ __forceinline__ unsigned long long mul2(unsigned long long a,
                                                   unsigned long long b) {
    unsigned long long r;
    asm("mul.rn.f32x2 %0, %1, %2;" : "=l"(r) : "l"(a), "l"(b));
    return r;
}

union F4U {
    float4 f;
    unsigned long long u[2];
    float s[4];
};

// ---- kernel 0: zero scratch ----
__global__ void zero_kernel() {
    int idx = blockIdx.x * blockDim.x + threadIdx.x;
    if (idx < H * D * D) g_C[idx] = 0.0f;
    if (idx < H * D) g_Z[idx] = 0.0f;
}

// ---- kernel 1: context numerator C[i][j] = sum_s exp(k[i,s]) * v[j,s], Z[i] = sum_s exp(k[i,s]) ----
__global__ __launch_bounds__(256) void ctx_kernel(const float* __restrict__ k,
                                                  const float* __restrict__ v) {
    __shared__ float ek[TS][D + 4];  // [s][i], exp(k)
    __shared__ float vs[TS][D + 4];  // [s][j]

    const int head = blockIdx.y;
    const int t = threadIdx.x;
    const float* kh = k + (size_t)head * D * S;
    const float* vh = v + (size_t)head * D * S;
    const int sblk = blockIdx.x * SCHUNK;

    const int ty = t >> 4, tx = t & 15;
    const int i0 = ty * 4, j0 = tx * 4;

    unsigned long long acc[4][2];
#pragma unroll
    for (int r = 0; r < 4; r++) { acc[r][0] = 0ull; acc[r][1] = 0ull; }

    float zloc = 0.0f;
    const int zi = t & 63;
    const int zs0 = (t >> 6) * 8;

    for (int tile = 0; tile < SCHUNK / TS; tile++) {
        const int sbase = sblk + tile * TS;
        // load + exp + transpose into smem (float4 over s, coalesced)
#pragma unroll
        for (int r = 0; r < 2; r++) {
            int idx = t + 256 * r;        // float4 index 0..511
            int i = idx >> 3;             // 0..63
            int s4 = (idx & 7) * 4;       // 0..28
            float4 kv = *reinterpret_cast<const float4*>(kh + (size_t)i * S + sbase + s4);
            ek[s4 + 0][i] = __expf(kv.x);
            ek[s4 + 1][i] = __expf(kv.y);
            ek[s4 + 2][i] = __expf(kv.z);
            ek[s4 + 3][i] = __expf(kv.w);
            float4 vv4 = *reinterpret_cast<const float4*>(vh + (size_t)i * S + sbase + s4);
            vs[s4 + 0][i] = vv4.x;
            vs[s4 + 1][i] = vv4.y;
            vs[s4 + 2][i] = vv4.z;
            vs[s4 + 3][i] = vv4.w;
        }
        __syncthreads();

        // partial Z accumulation (each thread: one row i, 8 s values)
#pragma unroll
        for (int s = 0; s < 8; s++) zloc += ek[zs0 + s][zi];

        // 64x64 outer-product accumulation over this s-tile (packed f32x2)
#pragma unroll
        for (int s = 0; s < TS; s++) {
            F4U ev, vv;
            ev.f = *reinterpret_cast<const float4*>(&ek[s][i0]);
            vv.f = *reinterpret_cast<const float4*>(&vs[s][j0]);
#pragma unroll
            for (int r = 0; r < 4; r++) {
                unsigned long long e2 = pack2(ev.s[r], ev.s[r]);
                fma2(acc[r][0], e2, vv.u[0]);
                fma2(acc[r][1], e2, vv.u[1]);
            }
        }
        __syncthreads();
    }

    // reduce partials into global scratch
    float* cptr = g_C + (size_t)head * D * D;
#pragma unroll
    for (int r = 0; r < 4; r++) {
        float x0, y0, x1, y1;
        unpack2(acc[r][0], x0, y0);
        unpack2(acc[r][1], x1, y1);
        atomicAdd(&cptr[(i0 + r) * D + j0 + 0], x0);
        atomicAdd(&cptr[(i0 + r) * D + j0 + 1], y0);
        atomicAdd(&cptr[(i0 + r) * D + j0 + 2], x1);
        atomicAdd(&cptr[(i0 + r) * D + j0 + 3], y1);
    }
    atomicAdd(&g_Z[head * D + zi], zloc);
}

// ---- kernel 2: out[j][s] = (scale/colsum[s]) * sum_i (C[i][j]/Z[i]) * exp(q[i][s]) ----
__global__ __launch_bounds__(256) void out_kernel(const float* __restrict__ q,
                                                  float* __restrict__ out) {
    __shared__ float Wt[D][D];       // Wt[i][j] = context[i][j]
    __shared__ float eq[D][D + 4];   // [i][s], exp(q)
    __shared__ float rz[D];
    __shared__ float rs[D];

    const int head = blockIdx.y;
    const int t = threadIdx.x;
    const int s0 = blockIdx.x * 64;
    const float* qh = q + (size_t)head * D * S;

    if (t < D) rz[t] = 1.0f / g_Z[head * D + t];
    __syncthreads();

    const float* Cg = g_C + (size_t)head * D * D;
#pragma unroll
    for (int r = 0; r < 16; r++) {
        int idx = t + 256 * r;   // 0..4095
        int i = idx >> 6;
        Wt[i][idx & 63] = Cg[idx] * rz[i];
    }

    // load q tile, exp, store [i][s]
#pragma unroll
    for (int r = 0; r < 4; r++) {
        int idx = t + 256 * r;        // float4 index 0..1023
        int i = idx >> 4;             // 0..63
        int s4 = (idx & 15) * 4;      // 0..60
        float4 qv = *reinterpret_cast<const float4*>(qh + (size_t)i * S + s0 + s4);
        float4 e;
        e.x = __expf(qv.x);
        e.y = __expf(qv.y);
        e.z = __expf(qv.z);
        e.w = __expf(qv.w);
        *reinterpret_cast<float4*>(&eq[i][s4]) = e;
    }
    __syncthreads();

    // column softmax denominators over d
    if (t < D) {
        float sum = 0.0f;
#pragma unroll
        for (int i = 0; i < D; i++) sum += eq[i][t];
        rs[t] = SCALE / sum;
    }
    __syncthreads();

    const int ty = t >> 4, tx = t & 15;
    const int j0 = ty * 4, sl0 = tx * 4;

    unsigned long long acc[4][2];
#pragma unroll
    for (int r = 0; r < 4; r++) { acc[r][0] = 0ull; acc[r][1] = 0ull; }

#pragma unroll
    for (int i = 0; i < D; i++) {
        F4U w, qv;
        w.f = *reinterpret_cast<const float4*>(&Wt[i][j0]);
        qv.f = *reinterpret_cast<const float4*>(&eq[i][sl0]);
#pragma unroll
        for (int r = 0; r < 4; r++) {
            unsigned long long w2 = pack2(w.s[r], w.s[r]);
            fma2(acc[r][0], w2, qv.u[0]);
            fma2(acc[r][1], w2, qv.u[1]);
        }
    }

    F4U rsv;
    rsv.f = *reinterpret_cast<const float4*>(&rs[sl0]);
    float* oh = out + (size_t)head * D * S;
#pragma unroll
    for (int r = 0; r < 4; r++) {
        F4U o;
        o.u[0] = mul2(acc[r][0], rsv.u[0]);
        o.u[1] = mul2(acc[r][1], rsv.u[1]);
        *reinterpret_cast<float4*>(oh + (size_t)(j0 + r) * S + s0 + sl0) = o.f;
    }
}

extern "C" void kernel_launch(void* const* d_in, const int* in_sizes, int n_in,
                              void* d_out, int out_size) {
    const float* q = (const float*)d_in[0];
    const float* k = (const float*)d_in[1];
    const float* v = (const float*)d_in[2];
    float* out = (float*)d_out;

    zero_kernel<<<(H * D * D + 255) / 256, 256>>>();
    dim3 g1(S / SCHUNK, H);   // 16 x 32 = 512 blocks
    ctx_kernel<<<g1, 256>>>(k, v);
    dim3 g2(S / 64, H);       // 128 x 32 = 4096 blocks
    out_kernel<<<g2, 256>>>(q, out);
}

// round 2
// speedup vs baseline: 1.0139x; 1.0139x over previous
#include <cuda_runtime.h>

#define S 8192
#define D 64
#define H 32        // b*n = 4*8
#define SCALE 0.125f // 64^-0.5
#define SCHUNK 512  // s elements per ctx block
#define TS 32       // s-tile inside ctx block

// Scratch (allocation-free rule: __device__ globals)
__device__ float g_C[H * D * D];  // per-head 64x64 context numerator
__device__ float g_Z[H * D];      // per-head row sums of exp(k)

// ---- packed f32x2 helpers ----
__device__ __forceinline__ unsigned long long pack2(float x, float y) {
    unsigned long long r;
    asm("mov.b64 %0, {%1, %2};" : "=l"(r) : "f"(x), "f"(y));
    return r;
}
__device__ __forceinline__ void unpack2(unsigned long long v, float &x, float &y) {
    asm("mov.b64 {%0, %1}, %2;" : "=f"(x), "=f"(y) : "l"(v));
}
__device__ __forceinline__ void fma2(unsigned long long &d, unsigned long long a,
                                     unsigned long long b) {
    asm("fma.rn.f32x2 %0, %1, %2, %0;" : "+l"(d) : "l"(a), "l"(b));
}
__device__ __forceinline__ unsigned long long mul2(unsigned long long a,
                                                   unsigned long long b) {
    unsigned long long r;
    asm("mul.rn.f32x2 %0, %1, %2;" : "=l"(r) : "l"(a), "l"(b));
    return r;
}

union F4U {
    float4 f;
    unsigned long long u[2];
    float s[4];
};

// ---- kernel 0: zero scratch ----
__global__ void zero_kernel() {
    int idx = blockIdx.x * blockDim.x + threadIdx.x;
    if (idx < H * D * D) g_C[idx] = 0.0f;
    if (idx < H * D) g_Z[idx] = 0.0f;
}

// ---- kernel 1: context numerator C[i][j] = sum_s exp(k[i,s]) * v[j,s], Z[i] = sum_s exp(k[i,s]) ----
__global__ __launch_bounds__(256) void ctx_kernel(const float* __restrict__ k,
                                                  const float* __restrict__ v) {
    __shared__ float ek[TS][D + 4];  // [s][i], exp(k)
    __shared__ float vs[TS][D + 4];  // [s][j]

    const int head = blockIdx.y;
    const int t = threadIdx.x;
    const float* kh = k + (size_t)head * D * S;
    const float* vh = v + (size_t)head * D * S;
    const int sblk = blockIdx.x * SCHUNK;

    const int ty = t >> 4, tx = t & 15;
    const int i0 = ty * 4, j0 = tx * 4;

    unsigned long long acc[4][2];
#pragma unroll
    for (int r = 0; r < 4; r++) { acc[r][0] = 0ull; acc[r][1] = 0ull; }

    float zloc = 0.0f;
    const int zi = t & 63;
    const int zs0 = (t >> 6) * 8;

    for (int tile = 0; tile < SCHUNK / TS; tile++) {
        const int sbase = sblk + tile * TS;
        // load + exp + transpose into smem (float4 over s, coalesced)
#pragma unroll
        for (int r = 0; r < 2; r++) {
            int idx = t + 256 * r;        // float4 index 0..511
            int i = idx >> 3;             // 0..63
            int s4 = (idx & 7) * 4;       // 0..28
            float4 kv = *reinterpret_cast<const float4*>(kh + (size_t)i * S + sbase + s4);
            ek[s4 + 0][i] = __expf(kv.x);
            ek[s4 + 1][i] = __expf(kv.y);
            ek[s4 + 2][i] = __expf(kv.z);
            ek[s4 + 3][i] = __expf(kv.w);
            float4 vv4 = *reinterpret_cast<const float4*>(vh + (size_t)i * S + sbase + s4);
            vs[s4 + 0][i] = vv4.x;
            vs[s4 + 1][i] = vv4.y;
            vs[s4 + 2][i] = vv4.z;
            vs[s4 + 3][i] = vv4.w;
        }
        __syncthreads();

        // partial Z accumulation (each thread: one row i, 8 s values)
#pragma unroll
        for (int s = 0; s < 8; s++) zloc += ek[zs0 + s][zi];

        // 64x64 outer-product accumulation over this s-tile (packed f32x2)
#pragma unroll
        for (int s = 0; s < TS; s++) {
            F4U ev, vv;
            ev.f = *reinterpret_cast<const float4*>(&ek[s][i0]);
            vv.f = *reinterpret_cast<const float4*>(&vs[s][j0]);
#pragma unroll
            for (int r = 0; r < 4; r++) {
                unsigned long long e2 = pack2(ev.s[r], ev.s[r]);
                fma2(acc[r][0], e2, vv.u[0]);
                fma2(acc[r][1], e2, vv.u[1]);
            }
        }
        __syncthreads();
    }

    // reduce partials into global scratch
    float* cptr = g_C + (size_t)head * D * D;
#pragma unroll
    for (int r = 0; r < 4; r++) {
        float x0, y0, x1, y1;
        unpack2(acc[r][0], x0, y0);
        unpack2(acc[r][1], x1, y1);
        atomicAdd(&cptr[(i0 + r) * D + j0 + 0], x0);
        atomicAdd(&cptr[(i0 + r) * D + j0 + 1], y0);
        atomicAdd(&cptr[(i0 + r) * D + j0 + 2], x1);
        atomicAdd(&cptr[(i0 + r) * D + j0 + 3], y1);
    }
    atomicAdd(&g_Z[head * D + zi], zloc);
}

// ---- kernel 2: out[j][s] = (scale/colsum[s]) * sum_i (C[i][j]/Z[i]) * exp(q[i][s]) ----
__global__ __launch_bounds__(256) void out_kernel(const float* __restrict__ q,
                                                  float* __restrict__ out) {
    __shared__ float Wt[D][D];       // Wt[i][j] = context[i][j]
    __shared__ float eq[D][D + 4];   // [i][s], exp(q)
    __shared__ float rz[D];
    __shared__ float rs[D];

    const int head = blockIdx.y;
    const int t = threadIdx.x;
    const int s0 = blockIdx.x * 64;
    const float* qh = q + (size_t)head * D * S;

    if (t < D) rz[t] = 1.0f / g_Z[head * D + t];
    __syncthreads();

    const float* Cg = g_C + (size_t)head * D * D;
#pragma unroll
    for (int r = 0; r < 16; r++) {
        int idx = t + 256 * r;   // 0..4095
        int i = idx >> 6;
        Wt[i][idx & 63] = Cg[idx] * rz[i];
    }

    // load q tile, exp, store [i][s]
#pragma unroll
    for (int r = 0; r < 4; r++) {
        int idx = t + 256 * r;        // float4 index 0..1023
        int i = idx >> 4;             // 0..63
        int s4 = (idx & 15) * 4;      // 0..60
        float4 qv = *reinterpret_cast<const float4*>(qh + (size_t)i * S + s0 + s4);
        float4 e;
        e.x = __expf(qv.x);
        e.y = __expf(qv.y);
        e.z = __expf(qv.z);
        e.w = __expf(qv.w);
        *reinterpret_cast<float4*>(&eq[i][s4]) = e;
    }
    __syncthreads();

    // column softmax denominators over d
    if (t < D) {
        float sum = 0.0f;
#pragma unroll
        for (int i = 0; i < D; i++) sum += eq[i][t];
        rs[t] = SCALE / sum;
    }
    __syncthreads();

    const int ty = t >> 4, tx = t & 15;
    const int j0 = ty * 4, sl0 = tx * 4;

    unsigned long long acc[4][2];
#pragma unroll
    for (int r = 0; r < 4; r++) { acc[r][0] = 0ull; acc[r][1] = 0ull; }

#pragma unroll
    for (int i = 0; i < D; i++) {
        F4U w, qv;
        w.f = *reinterpret_cast<const float4*>(&Wt[i][j0]);
        qv.f = *reinterpret_cast<const float4*>(&eq[i][sl0]);
#pragma unroll
        for (int r = 0; r < 4; r++) {
            unsigned long long w2 = pack2(w.s[r], w.s[r]);
            fma2(acc[r][0], w2, qv.u[0]);
            fma2(acc[r][1], w2, qv.u[1]);
        }
    }

    F4U rsv;
    rsv.f = *reinterpret_cast<const float4*>(&rs[sl0]);
    float* oh = out + (size_t)head * D * S;
#pragma unroll
    for (int r = 0; r < 4; r++) {
        F4U o;
        o.u[0] = mul2(acc[r][0], rsv.u[0]);
        o.u[1] = mul2(acc[r][1], rsv.u[1]);
        *reinterpret_cast<float4*>(oh + (size_t)(j0 + r) * S + s0 + sl0) = o.f;
    }
}

extern "C" void kernel_launch(void* const* d_in, const int* in_sizes, int n_in,
                              void* d_out, int out_size) {
    const float* q = (const float*)d_in[0];
    const float* k = (const float*)d_in[1];
    const float* v = (const float*)d_in[2];
    float* out = (float*)d_out;

    zero_kernel<<<(H * D * D + 255) / 256, 256>>>();
    dim3 g1(S / SCHUNK, H);   // 16 x 32 = 512 blocks
    ctx_kernel<<<g1, 256>>>(k, v);
    dim3 g2(S / 64, H);       // 128 x 32 = 4096 blocks
    out_kernel<<<g2, 256>>>(q, out);
}